// round 10
// baseline (speedup 1.0000x reference)
#include <cuda_runtime.h>
#include <cuda_bf16.h>
#include <cstdint>

// ---------------- problem constants ----------------
#define SEQ   2048
#define EDIM  512
#define HDIM  256
#define TTAGS 32
#define TSTART 30
#define TSTOP  31
#define NEGV  (-10000.0f)

// ---------------- device scratch (no allocs allowed) ----------------
__device__ float g_px[2][SEQ][1024];     // input projections (bias fused), per dir
__device__ float g_h[2][SEQ][HDIM];      // lstm hidden outputs, per dir
__device__ float g_feats[SEQ][TTAGS];    // tag scores
__device__ float g_wtagT[EDIM][TTAGS];   // transposed tag weights
__device__ int   g_bptr[SEQ][TTAGS];     // viterbi backpointers

// ---------------- small helpers ----------------
__device__ __forceinline__ unsigned long long pack2f(float x, float y) {
    unsigned long long r;
    asm("mov.b64 %0, {%1, %2};" : "=l"(r) : "f"(x), "f"(y));
    return r;
}
__device__ __forceinline__ float2 unpack2f(unsigned long long v) {
    float2 r;
    asm("mov.b64 {%0, %1}, %2;" : "=f"(r.x), "=f"(r.y) : "l"(v));
    return r;
}
__device__ __forceinline__ void fma2(unsigned long long& d, unsigned long long a,
                                     unsigned long long b) {
    asm("fma.rn.f32x2 %0, %1, %2, %0;" : "+l"(d) : "l"(a), "l"(b));
}
__device__ __forceinline__ unsigned smem_u32(const void* p) {
    unsigned a;
    asm("{ .reg .u64 t; cvta.to.shared.u64 t, %1; cvt.u32.u64 %0, t; }"
        : "=r"(a) : "l"(p));
    return a;
}
__device__ __forceinline__ unsigned mapa_u32(unsigned addr, int rank) {
    unsigned ra;
    asm("mapa.shared::cluster.u32 %0, %1, %2;" : "=r"(ra) : "r"(addr), "r"(rank));
    return ra;
}
__device__ __forceinline__ void st_cluster_addr_f32(unsigned raddr, float v) {
    asm volatile("st.shared::cluster.f32 [%0], %1;" :: "r"(raddr), "f"(v)
                 : "memory");
}
__device__ __forceinline__ void cluster_sync_() {
    asm volatile("barrier.cluster.arrive.aligned;" ::: "memory");
    asm volatile("barrier.cluster.wait.aligned;" ::: "memory");
}
__device__ __forceinline__ float sigmoidf_(float x) {
    return 1.0f / (1.0f + __expf(-x));
}
// tanh with __expf accuracy class (~1e-7 abs err) but no software-branch
// polynomial: 1 - 2/(e^{2x}+1). Large |x| limits handled by inf/0 naturally.
__device__ __forceinline__ float tanh_fast(float x) {
    float e = __expf(2.0f * x);
    return 1.0f - __fdividef(2.0f, e + 1.0f);
}

// ============================================================================
// Kernel 1: px[dir][t][row] = sum_e emb[sent[t]][e] * w_ih[dir][row][e] + b[row]
// 64x64 output tile, K-tile 16, 256 threads, 4x4 microtile.
// ============================================================================
__global__ __launch_bounds__(256)
void px_gemm(const int* __restrict__ sent, const float* __restrict__ embed,
             const float* __restrict__ w_ih_f, const float* __restrict__ b_f,
             const float* __restrict__ w_ih_b, const float* __restrict__ b_b)
{
    int dir = blockIdx.z;
    const float* W  = dir ? w_ih_b : w_ih_f;
    const float* Bv = dir ? b_b    : b_f;
    int t0 = blockIdx.x * 64;
    int r0 = blockIdx.y * 64;

    __shared__ float As[16][64];
    __shared__ float Bs[16][68];
    __shared__ int   ssent[64];

    int tid = threadIdx.x;
    if (tid < 64) ssent[tid] = sent[t0 + tid];
    __syncthreads();

    int tx = tid & 15, ty = tid >> 4;
    float acc[4][4] = {};

    for (int k0 = 0; k0 < EDIM; k0 += 16) {
#pragma unroll
        for (int l = 0; l < 4; l++) {
            int lin = tid + l * 256;
            int kk = lin & 15, ii = lin >> 4;
            As[kk][ii] = embed[(size_t)ssent[ii] * EDIM + k0 + kk];
            Bs[kk][ii] = W[(size_t)(r0 + ii) * EDIM + k0 + kk];
        }
        __syncthreads();
#pragma unroll
        for (int kk = 0; kk < 16; kk++) {
            float a[4], b[4];
#pragma unroll
            for (int i = 0; i < 4; i++) a[i] = As[kk][ty * 4 + i];
#pragma unroll
            for (int j = 0; j < 4; j++) b[j] = Bs[kk][tx * 4 + j];
#pragma unroll
            for (int i = 0; i < 4; i++)
#pragma unroll
                for (int j = 0; j < 4; j++) acc[i][j] += a[i] * b[j];
        }
        __syncthreads();
    }
#pragma unroll
    for (int i = 0; i < 4; i++)
#pragma unroll
        for (int j = 0; j < 4; j++) {
            int t = t0 + ty * 4 + i;
            int r = r0 + tx * 4 + j;
            g_px[dir][t][r] = acc[i][j] + Bv[r];
        }
}

// ============================================================================
// Kernel 2: transpose w_tag [32,512] -> g_wtagT [512,32]
// ============================================================================
__global__ void wtagT_kernel(const float* __restrict__ w_tag)
{
    int idx = blockIdx.x * blockDim.x + threadIdx.x;
    if (idx < TTAGS * EDIM) {
        int tag = idx >> 9;
        int e   = idx & 511;
        g_wtagT[e][tag] = w_tag[idx];
    }
}

// ============================================================================
// Kernel 3: BiLSTM recurrence. cluster.sync skeleton (passed 4x) + merged
// warp0 reduce (round-9 win) + this round's critical-chain shavings:
//  - red_sh transposed to [128][4]: warp0 reduce = 4x LDS.128 instead of
//    16x LDS.32 (same crossbar traffic, -12 issue slots on critical warp)
//  - tanhf -> tanh_fast (expf-based, no software polynomial/branches)
//  - mapa hoisted: rbase[8] precomputed once; DSMEM stores issued before
//    the global STG so their flight starts earlier
// ============================================================================
__global__ void __cluster_dims__(8, 1, 1) __launch_bounds__(512, 1)
lstm_kernel(const float* __restrict__ w_hh_f, const float* __restrict__ w_hh_b,
            const float* __restrict__ h0, const float* __restrict__ c0)
{
    int dir  = blockIdx.x >> 3;
    int rank = blockIdx.x & 7;
    const float* W  = dir ? w_hh_b : w_hh_f;
    const float* px = &g_px[dir][0][0];
    float* hout     = &g_h[dir][0][0];

    int tid  = threadIdx.x;
    int ks   = tid >> 7;        // 0..3  (k slice of 64)
    int r    = tid & 127;       // 0..127 (gate row within CTA)
    int grow = (r >> 5) * 256 + rank * 32 + (r & 31);   // gate row in [0,1024)

    __shared__ __align__(16) float h_sh[2][HDIM];
    __shared__ __align__(16) float red_sh[128][4];

    // load weight slice into registers, packed as f32x2
    unsigned long long w2[32];
    {
        const float2* wp = (const float2*)(W + (size_t)grow * HDIM + ks * 64);
#pragma unroll
        for (int i = 0; i < 32; i++) {
            float2 v = wp[i];
            w2[i] = pack2f(v.x, v.y);
        }
    }

    // initial state
    if (tid < HDIM) h_sh[0][tid] = h0[dir * HDIM + tid];
    float c = 0.0f;
    if (tid < 32) c = c0[dir * HDIM + rank * 32 + tid];

    // hoisted remote base addresses of h_sh[0][0] in each rank's CTA
    unsigned hbase = smem_u32(&h_sh[0][0]);
    unsigned rbase[8];
#pragma unroll
    for (int cc = 0; cc < 8; cc++) rbase[cc] = mapa_u32(hbase, cc);

    // warp0: prefetch px for step 0 (the 4 gate rows of unit `tid`)
    float px4_0 = 0.f, px4_1 = 0.f, px4_2 = 0.f, px4_3 = 0.f;
    if (tid < 32) {
        int t0i = dir ? (SEQ - 1) : 0;
        const float* p0 = &px[(size_t)t0i * 1024 + rank * 32 + tid];
        px4_0 = __ldg(p0);
        px4_1 = __ldg(p0 + 256);
        px4_2 = __ldg(p0 + 512);
        px4_3 = __ldg(p0 + 768);
    }

    __syncthreads();
    cluster_sync_();

    int p = 0;
    for (int step = 0; step < SEQ; ++step) {
        int t = dir ? (SEQ - 1 - step) : step;

        // matvec partial: 64 MACs via 32 packed FFMA2
        unsigned long long a0 = 0ull, a1 = 0ull;
        const ulonglong2* hp = (const ulonglong2*)&h_sh[p][ks * 64];
#pragma unroll
        for (int i = 0; i < 16; i += 2) {
            ulonglong2 u = hp[i];
            ulonglong2 v = hp[i + 1];
            fma2(a0, w2[2 * i], u.x);
            fma2(a1, w2[2 * i + 1], u.y);
            fma2(a0, w2[2 * i + 2], v.x);
            fma2(a1, w2[2 * i + 3], v.y);
        }
        float2 f0 = unpack2f(a0), f1 = unpack2f(a1);
        red_sh[r][ks] = (f0.x + f0.y) + (f1.x + f1.y);
        __syncthreads();

        // warp0: vector reduce + activations + cell/hidden + cluster broadcast
        if (tid < 32) {
            float4 g0 = *(const float4*)red_sh[tid];
            float4 g1 = *(const float4*)red_sh[32 + tid];
            float4 g2 = *(const float4*)red_sh[64 + tid];
            float4 g3 = *(const float4*)red_sh[96 + tid];
            float v0 = (g0.x + g0.y) + (g0.z + g0.w) + px4_0;
            float v1 = (g1.x + g1.y) + (g1.z + g1.w) + px4_1;
            float v2 = (g2.x + g2.y) + (g2.z + g2.w) + px4_2;
            float v3 = (g3.x + g3.y) + (g3.z + g3.w) + px4_3;
            float ai = sigmoidf_(v0);
            float af = sigmoidf_(v1);
            float ag = tanh_fast(v2);
            float ao = sigmoidf_(v3);
            c = af * c + ai * ag;
            float hn = ao * tanh_fast(c);

            // DSMEM broadcast first (starts the cross-CTA flight earliest)
            unsigned off = (unsigned)((((p ^ 1) * HDIM) + rank * 32 + tid) * 4);
#pragma unroll
            for (int cc = 0; cc < 8; cc++)
                st_cluster_addr_f32(rbase[cc] + off, hn);

            hout[(size_t)t * HDIM + rank * 32 + tid] = hn;

            // prefetch px for next step; LDG latency hides under cluster.sync
            if (step + 1 < SEQ) {
                int tn = dir ? (SEQ - 2 - step) : (step + 1);
                const float* p0 = &px[(size_t)tn * 1024 + rank * 32 + tid];
                px4_0 = __ldg(p0);
                px4_1 = __ldg(p0 + 256);
                px4_2 = __ldg(p0 + 512);
                px4_3 = __ldg(p0 + 768);
            }
        }
        cluster_sync_();
        p ^= 1;
    }
}

// ============================================================================
// Kernel 4: feats[t][tag] = [h_f(t) | h_b(t)] . w_tag[tag] + b_tag[tag]
// one block per timestep, 128 threads (32 tags x 4 partials)
// ============================================================================
__global__ __launch_bounds__(128)
void proj_kernel(const float* __restrict__ b_tag)
{
    int t = blockIdx.x;
    __shared__ float hs[2 * HDIM];
    __shared__ float red[4][TTAGS];
    int tid = threadIdx.x;
    for (int i = tid; i < HDIM; i += 128) {
        hs[i]        = g_h[0][t][i];
        hs[HDIM + i] = g_h[1][t][i];
    }
    __syncthreads();
    int tag = tid & 31, part = tid >> 5;
    float s = 0.0f;
    const float* hv = hs + part * 128;
    const float* wT = &g_wtagT[part * 128][tag];
#pragma unroll 8
    for (int j = 0; j < 128; j++) s += hv[j] * wT[j * TTAGS];
    red[part][tag] = s;
    __syncthreads();
    if (tid < TTAGS)
        g_feats[t][tid] = red[0][tid] + red[1][tid] + red[2][tid] + red[3][tid] +
                          b_tag[tid];
}

// ============================================================================
// Kernel 5: Viterbi forward + backtrack. Single warp (feat prefetch kept).
// ============================================================================
__global__ __launch_bounds__(32)
void viterbi_kernel(const float* __restrict__ trans, float* __restrict__ out,
                    int out_size)
{
    const unsigned FULL = 0xffffffffu;
    int lane = threadIdx.x;

    float tr[TTAGS];
#pragma unroll
    for (int j = 0; j < TTAGS; j++) tr[j] = trans[lane * TTAGS + j];

    float fv = (lane == TSTART) ? 0.0f : NEGV;
    float feat = g_feats[0][lane];

    for (int t = 0; t < SEQ; t++) {
        float feat_next = (t + 1 < SEQ) ? g_feats[t + 1][lane] : 0.0f;
        float b0 = -1e30f, b1 = -1e30f, b2 = -1e30f, b3 = -1e30f;
        int i0 = 0, i1 = 8, i2 = 16, i3 = 24;
#pragma unroll
        for (int j = 0; j < 8; j++) {
            float s0 = __shfl_sync(FULL, fv, j)      + tr[j];
            float s1 = __shfl_sync(FULL, fv, j + 8)  + tr[j + 8];
            float s2 = __shfl_sync(FULL, fv, j + 16) + tr[j + 16];
            float s3 = __shfl_sync(FULL, fv, j + 24) + tr[j + 24];
            if (s0 > b0) { b0 = s0; i0 = j; }
            if (s1 > b1) { b1 = s1; i1 = j + 8; }
            if (s2 > b2) { b2 = s2; i2 = j + 16; }
            if (s3 > b3) { b3 = s3; i3 = j + 24; }
        }
        float best = b0; int bj = i0;
        if (b1 > best) { best = b1; bj = i1; }
        if (b2 > best) { best = b2; bj = i2; }
        if (b3 > best) { best = b3; bj = i3; }
        g_bptr[t][lane] = bj;
        fv = best + feat;
        feat = feat_next;
    }

    // terminal: fv + transitions[STOP][prev]
    float term = fv + trans[TSTOP * TTAGS + lane];
    float bv = term; int bi = lane;
#pragma unroll
    for (int off = 16; off >= 1; off >>= 1) {
        float ov = __shfl_xor_sync(FULL, bv, off);
        int   oi = __shfl_xor_sync(FULL, bi, off);
        if (ov > bv || (ov == bv && oi < bi)) { bv = ov; bi = oi; }
    }
    if (lane == 0 && out_size > 0) out[0] = bv;

    // backtrack: tag_seq[S-1] = best_last; tag_seq[t-1] = bptr[t][tag_seq[t]]
    int tag = bi;
    for (int t0 = SEQ - 16; t0 >= 0; t0 -= 16) {
        int rows[16];
#pragma unroll
        for (int k = 0; k < 16; k++) rows[k] = g_bptr[t0 + k][lane];
#pragma unroll
        for (int k = 15; k >= 0; k--) {
            int t = t0 + k;
            if (lane == 0 && 1 + t < out_size) out[1 + t] = (float)tag;
            tag = __shfl_sync(FULL, rows[k], tag);
        }
    }
}

// ============================================================================
// launcher
// ============================================================================
extern "C" void kernel_launch(void* const* d_in, const int* in_sizes, int n_in,
                              void* d_out, int out_size)
{
    const int*   sent    = (const int*)d_in[0];
    const float* embed   = (const float*)d_in[1];
    const float* w_ih_f  = (const float*)d_in[2];
    const float* w_hh_f  = (const float*)d_in[3];
    const float* b_f     = (const float*)d_in[4];
    const float* w_ih_b  = (const float*)d_in[5];
    const float* w_hh_b  = (const float*)d_in[6];
    const float* b_b     = (const float*)d_in[7];
    const float* w_tag   = (const float*)d_in[8];
    const float* b_tag   = (const float*)d_in[9];
    const float* trans   = (const float*)d_in[10];
    const float* h0      = (const float*)d_in[11];
    const float* c0      = (const float*)d_in[12];
    float* out = (float*)d_out;

    dim3 g1(SEQ / 64, 1024 / 64, 2);
    px_gemm<<<g1, 256>>>(sent, embed, w_ih_f, b_f, w_ih_b, b_b);
    wtagT_kernel<<<(TTAGS * EDIM + 511) / 512, 512>>>(w_tag);
    lstm_kernel<<<16, 512>>>(w_hh_f, w_hh_b, h0, c0);
    proj_kernel<<<SEQ, 128>>>(b_tag);
    viterbi_kernel<<<1, 32>>>(trans, out, out_size);
}